// round 17
// baseline (speedup 1.0000x reference)
#include <cuda_runtime.h>
#include <stdint.h>

#define KEHALF   7.199822675975274f
#define CUTOFF   10.0f
#define L2E      1.4426950408889634f
#define ZMAX     94
#define LUT_REP  32
#define CHUNK    4
#define NTHREADS 1024

// per-atom z-index bytes (Z-1), built by prep kernel
__device__ __align__(16) uint8_t g_ztab[131072];

__device__ __forceinline__ float softplus_f(float x) {
    return (x > 20.0f) ? x : log1pf(__expf(x));
}

__global__ void k_prep(const float* __restrict__ Z,
                       int N, float* __restrict__ y, int M) {
    int i = blockIdx.x * blockDim.x + threadIdx.x;
    if (i < M) y[i] = 0.0f;
    if (i < N && i < 131072)
        g_ztab[i] = (uint8_t)((int)(__ldg(Z + i) + 0.5f) - 1);
}

__device__ __forceinline__ void prefetch_l2(const void* p) {
    asm volatile("prefetch.global.L2 [%0];" :: "l"(p));
}

__device__ __forceinline__ void prefetch_iter(const float4* __restrict__ rv,
                                              const int* __restrict__ ii,
                                              const int* __restrict__ jj,
                                              int ep) {
    const float4* rp = rv + (ep >> 2) * 3;
    prefetch_l2(rp);
    prefetch_l2(rp + 2);      // thread's 48B r-span: both possible lines
    prefetch_l2(ii + ep);
    prefetch_l2(jj + ep);
}

struct Chunk {
    float4 p0, p1, p2;   // 12 floats = 4 edges x (rx,ry,rz)
    int4   iv, jv;
};

__device__ __forceinline__ Chunk load_chunk(const float4* __restrict__ rv,
                                            const int* __restrict__ ii,
                                            const int* __restrict__ jj,
                                            int e0) {
    Chunk c;
    int fi = (e0 >> 2) * 3;
    c.p0 = __ldcs(rv + fi + 0);
    c.p1 = __ldcs(rv + fi + 1);
    c.p2 = __ldcs(rv + fi + 2);
    c.iv = __ldcs((const int4*)(ii + e0));
    c.jv = __ldcs((const int4*)(jj + e0));
    return c;
}

// cf layout: [0..3]=b, [4..7]=c, [8]=thr2 (thr squared), [9]=thr
__device__ __forceinline__ void do_edge(
    float rx, float ry, float rz, int zi, int zj, float zsum,
    float thr2, const float* __restrict__ cf,
    float* bins, const int* __restrict__ im, int iatom)
{
    float s = fmaf(rx, rx, fmaf(ry, ry, rz * rz));   // d^2
    float q = (zsum * zsum) * s;                      // t^2

    // Squared-space survival test (exact): t < thr && d < CUTOFF.
    // Non-survivors contribute exactly 0 (all exp2 terms underflow to 0.0f),
    // matching the fp32 reference.
    if (q < thr2 && s < CUTOFF * CUTOFF) {            // ~0.3% of edges
        float rs = rsqrtf(s);                         // MUFU only on survivors
        float d  = s * rs;
        float t  = zsum * d;
        float f = cf[4] * exp2f(-cf[0] * t) + cf[5] * exp2f(-cf[1] * t)
                + cf[6] * exp2f(-cf[2] * t) + cf[7] * exp2f(-cf[3] * t);
        float u  = d * (1.0f / CUTOFF);
        float u3 = u * u * u;
        float p  = fmaf(-6.0f, u, 15.0f);
        p        = fmaf(p, u, -10.0f);
        float fc = fmaf(u3, p, 1.0f);
        float Zi = (float)(zi + 1), Zj = (float)(zj + 1);
        float ee = KEHALF * f * fc * Zi * Zj * rs;
        if (ee != 0.0f) atomicAdd(&bins[im[iatom]], ee);
    }
}

__device__ __forceinline__ void process_chunk(
    const Chunk& c, const uint8_t* __restrict__ ztab,
    const float* __restrict__ zlut, float thr2, const float* __restrict__ cf,
    float* bins, const int* __restrict__ im, int lane)
{
    int ia[CHUNK] = {c.iv.x, c.iv.y, c.iv.z, c.iv.w};
    int ja[CHUNK] = {c.jv.x, c.jv.y, c.jv.z, c.jv.w};
    float fx[12]  = {c.p0.x, c.p0.y, c.p0.z, c.p0.w,
                     c.p1.x, c.p1.y, c.p1.z, c.p1.w,
                     c.p2.x, c.p2.y, c.p2.z, c.p2.w};

    int zi[CHUNK], zj[CHUNK];
    #pragma unroll
    for (int k = 0; k < CHUNK; k++) {
        zi[k] = ztab[ia[k]];
        zj[k] = ztab[ja[k]];
    }
    float zs[CHUNK];
    #pragma unroll
    for (int k = 0; k < CHUNK; k++)
        zs[k] = zlut[zi[k] * LUT_REP + lane] + zlut[zj[k] * LUT_REP + lane];

    #pragma unroll
    for (int k = 0; k < CHUNK; k++)
        do_edge(fx[3 * k], fx[3 * k + 1], fx[3 * k + 2],
                zi[k], zj[k], zs[k], thr2, cf, bins, im, ia[k]);
}

__global__ __launch_bounds__(NTHREADS, 1) void k_edge(
    const float* __restrict__ r,
    const int*   __restrict__ ii,
    const int*   __restrict__ jj,
    const int*   __restrict__ im,
    const float* __restrict__ adiv,
    const float* __restrict__ apow,
    const float* __restrict__ av,
    const float* __restrict__ cv,
    int N, int E, float* __restrict__ y, int M)
{
    extern __shared__ char smem_raw[];
    float*   bins = (float*)smem_raw;
    float*   cf   = bins + M;                 // 16 floats (coef block)
    float*   zlut = cf + 16;
    uint8_t* ztab = (uint8_t*)(((uintptr_t)(zlut + ZMAX * LUT_REP) + 15) & ~(uintptr_t)15);

    int tid  = threadIdx.x;
    int lane = tid & 31;

    int stride = gridDim.x * blockDim.x * CHUNK;
    int E4     = E & ~(CHUNK - 1);
    const float4* rv = (const float4*)r;
    int e0 = (blockIdx.x * blockDim.x + tid) * CHUNK;

    // Prologue prefetch: cover iterations 1 and 2 before the cold start
    // (their real LDGs would otherwise take the full DRAM round-trip).
    if (e0 + stride     < E4) prefetch_iter(rv, ii, jj, e0 + stride);
    if (e0 + 2 * stride < E4) prefetch_iter(rv, ii, jj, e0 + 2 * stride);

    for (int b = tid; b < M; b += blockDim.x) bins[b] = 0.0f;

    if (tid == 0) {
        float sp_adiv = softplus_f(adiv[0]);
        float a0 = softplus_f(av[0]), a1 = softplus_f(av[1]);
        float a2 = softplus_f(av[2]), a3 = softplus_f(av[3]);
        float c0 = softplus_f(cv[0]), c1 = softplus_f(cv[1]);
        float c2 = softplus_f(cv[2]), c3 = softplus_f(cv[3]);
        float cinv = 1.0f / (fabsf(c0) + fabsf(c1) + fabsf(c2) + fabsf(c3));
        float b0 = a0 * sp_adiv * L2E, b1 = a1 * sp_adiv * L2E;
        float b2 = a2 * sp_adiv * L2E, b3 = a3 * sp_adiv * L2E;
        cf[0] = b0; cf[1] = b1; cf[2] = b2; cf[3] = b3;
        cf[4] = c0 * cinv; cf[5] = c1 * cinv; cf[6] = c2 * cinv; cf[7] = c3 * cinv;
        float bmin = fminf(fminf(b0, b1), fminf(b2, b3));
        float thr  = 151.0f / bmin;  // t >= thr => every exp2 term is exactly 0.0f
        cf[8] = thr * thr;
        cf[9] = thr;
    }

    // bank-replicated z-LUT: zlut[zi*32 + lane] -> bank == lane, conflict-free
    {
        float spw = softplus_f(apow[0]);
        for (int k = tid; k < ZMAX * LUT_REP; k += blockDim.x) {
            int zi = k / LUT_REP;
            zlut[k] = exp2f(spw * log2f((float)(zi + 1)));
        }
    }

    {   // stage pre-packed byte table into smem (100KB per CTA, int4)
        const int4* src = (const int4*)g_ztab;
        int4*       dst = (int4*)ztab;
        int n16 = N >> 4;
        for (int k = tid; k < n16; k += blockDim.x) dst[k] = src[k];
        for (int k = (n16 << 4) + tid; k < N; k += blockDim.x) ztab[k] = g_ztab[k];
    }

    __syncthreads();

    float thr2 = cf[8];
    int e = e0;

    // ---- 2-deep register pipeline + distance-3 L2 prefetch ----
    if (e < E4) {
        Chunk cur = load_chunk(rv, ii, jj, e);
        while (true) {
            int  en   = e + stride;
            bool hasn = (en < E4);

            // L2 prefetch for iteration n+3 (no regs, no scoreboard):
            int ep = e + 3 * stride;
            if (ep < E4) prefetch_iter(rv, ii, jj, ep);

            Chunk nxt;
            if (hasn) nxt = load_chunk(rv, ii, jj, en);   // in flight during compute
            process_chunk(cur, ztab, zlut, thr2, cf, bins, im, lane);
            if (!hasn) break;
            cur = nxt;
            e   = en;
        }
    }

    // scalar tail (E not multiple of CHUNK)
    if (blockIdx.x == 0) {
        for (int t = E4 + tid; t < E; t += blockDim.x) {
            int i = ii[t], j = jj[t];
            int zi = ztab[i], zj = ztab[j];
            float zsum = zlut[zi * LUT_REP + lane] + zlut[zj * LUT_REP + lane];
            do_edge(r[3 * t], r[3 * t + 1], r[3 * t + 2],
                    zi, zj, zsum, thr2, cf, bins, im, i);
        }
    }

    __syncthreads();
    for (int b = tid; b < M; b += blockDim.x) {
        float v = bins[b];
        if (v != 0.0f) atomicAdd(&y[b], v);
    }
}

extern "C" void kernel_launch(void* const* d_in, const int* in_sizes, int n_in,
                              void* d_out, int out_size) {
    const float* Z    = (const float*)d_in[0];
    const float* r    = (const float*)d_in[1];
    const int*   ii   = (const int*)  d_in[2];
    const int*   jj   = (const int*)  d_in[3];
    const int*   im   = (const int*)  d_in[4];
    const float* adiv = (const float*)d_in[5];
    const float* apow = (const float*)d_in[6];
    const float* av   = (const float*)d_in[7];
    const float* cv   = (const float*)d_in[8];

    int N = in_sizes[0];
    int E = in_sizes[2];
    int M = out_size;
    float* y = (float*)d_out;

    int prep_n = (N > M ? N : M);
    k_prep<<<(prep_n + 255) / 256, 256>>>(Z, N, y, M);

    int sm_count = 148;
    cudaDeviceGetAttribute(&sm_count, cudaDevAttrMultiProcessorCount, 0);

    size_t smem = (size_t)M * 4 + 16 * 4 + (size_t)ZMAX * LUT_REP * 4 + 32 + (size_t)N;
    cudaFuncSetAttribute(k_edge,
                         cudaFuncAttributeMaxDynamicSharedMemorySize, (int)smem);
    k_edge<<<sm_count, NTHREADS, smem>>>(
        r, ii, jj, im, adiv, apow, av, cv, N, E, y, M);
}